// round 13
// baseline (speedup 1.0000x reference)
#include <cuda_runtime.h>
#include <math.h>

#define NB 4
#define NPTS 8192
#define NS 1024
#define NK 32
#define R2C 0.01f
#define FPS_CLU 8
#define THR 256
#define FPS_ACT 128                       // active FPS threads per CTA
#define PPT (NPTS / FPS_CLU / FPS_ACT)    // 8 points per thread
#define NPAIR (PPT / 2)                   // 4 pairs
#define NSLOT (FPS_CLU * (FPS_ACT / 32))  // 32 mailbox slots = 32 lanes
#define NFPS_CTA (NB * FPS_CLU)           // 32 FPS CTAs
#define NSA_CTA 64                        // 64 SA CTAs (8 warps x 8 centroids)
#define SMEM_BYTES (3 * NPTS * 4)         // 96 KB

// ---- device scratch (no allocations allowed) ----
__device__ int g_fps[NB * NS];            // stores far+1 (0 = not ready)

// ---- packed f32x2 helpers (per-half IEEE rn => bitwise == scalar) ----
__device__ __forceinline__ unsigned long long pk2(float lo, float hi) {
    unsigned long long r;
    asm("mov.b64 %0, {%1, %2};" : "=l"(r) : "f"(lo), "f"(hi));
    return r;
}
__device__ __forceinline__ void upk2(float& lo, float& hi, unsigned long long v) {
    asm("mov.b64 {%0, %1}, %2;" : "=f"(lo), "=f"(hi) : "l"(v));
}
__device__ __forceinline__ unsigned long long addx2(unsigned long long a, unsigned long long b) {
    unsigned long long r;
    asm("add.rn.f32x2 %0, %1, %2;" : "=l"(r) : "l"(a), "l"(b));
    return r;
}
__device__ __forceinline__ unsigned long long mulx2(unsigned long long a, unsigned long long b) {
    unsigned long long r;
    asm("mul.rn.f32x2 %0, %1, %2;" : "=l"(r) : "l"(a), "l"(b));
    return r;
}

// ---- cluster helpers ----
__device__ __forceinline__ unsigned smem_u32(const void* p) {
    return (unsigned)__cvta_generic_to_shared(p);
}
__device__ __forceinline__ unsigned mapa_rank(unsigned addr, unsigned rank) {
    unsigned r;
    asm("mapa.shared::cluster.u32 %0, %1, %2;" : "=r"(r) : "r"(addr), "r"(rank));
    return r;
}
__device__ __forceinline__ void st_async_u64(unsigned raddr, unsigned long long v, unsigned rmbar) {
    asm volatile("st.async.shared::cluster.mbarrier::complete_tx::bytes.b64 [%0], %1, [%2];"
                 :: "r"(raddr), "l"(v), "r"(rmbar) : "memory");
}
__device__ __forceinline__ void mbar_init(unsigned mbar, unsigned cnt) {
    asm volatile("mbarrier.init.shared.b64 [%0], %1;" :: "r"(mbar), "r"(cnt) : "memory");
}
__device__ __forceinline__ void mbar_expect_tx(unsigned mbar, unsigned bytes) {
    asm volatile("mbarrier.arrive.expect_tx.shared.b64 _, [%0], %1;" :: "r"(mbar), "r"(bytes) : "memory");
}
__device__ __forceinline__ void mbar_wait(unsigned mbar, unsigned parity) {
    asm volatile(
        "{\n\t.reg .pred P;\n"
        "LW%=:\n\t"
        "mbarrier.try_wait.parity.acquire.cluster.shared::cta.b64 P, [%0], %1;\n\t"
        "@P bra LD%=;\n\t"
        "bra LW%=;\n"
        "LD%=:\n\t}"
        :: "r"(mbar), "r"(parity) : "memory");
}

// ============================================================
// FPS role: clusters 0..NB-1 (CTAs 0..31). Warps 0-3 active.
// st.async + mbarrier exchange (R7/R11-proven). Exact fp32 order.
// ============================================================
__device__ __noinline__ void fps_role(const float* __restrict__ xyz, float* smf)
{
    float* sx = smf;
    float* sy = smf + NPTS;
    float* sz = smf + 2 * NPTS;
    __shared__ unsigned long long s_mbox[2][NSLOT];
    __shared__ unsigned long long s_mbar[2];

    int tid = threadIdx.x;
    int lane = tid & 31, w = tid >> 5;
    int rank = blockIdx.x & (FPS_CLU - 1);
    int b = blockIdx.x / FPS_CLU;
    const float* p = xyz + (size_t)b * 3 * NPTS;

    // full coordinate copy into smem (centroid lookup) — all 256 threads
    const float4* p4x = (const float4*)p;
    const float4* p4y = (const float4*)(p + NPTS);
    const float4* p4z = (const float4*)(p + 2 * NPTS);
    for (int i = tid; i < NPTS / 4; i += THR) {
        ((float4*)sx)[i] = p4x[i];
        ((float4*)sy)[i] = p4y[i];
        ((float4*)sz)[i] = p4z[i];
    }

    if (tid == 0) {
        mbar_init(smem_u32(&s_mbar[0]), 1);
        mbar_init(smem_u32(&s_mbar[1]), 1);
    }
    __syncthreads();
    asm volatile("barrier.cluster.arrive.aligned;" ::: "memory");
    asm volatile("barrier.cluster.wait.aligned;" ::: "memory");

    if (tid < FPS_ACT) {
        // this thread's 8 points (register-resident, packed)
        int base = rank * (NPTS / FPS_CLU) + tid * PPT;
        unsigned long long Px[NPAIR], Py[NPAIR], Pz[NPAIR];
#pragma unroll
        for (int r = 0; r < PPT / 4; r++) {
            int v4i = base / 4 + r;
            float4 vx = p4x[v4i];
            float4 vy = p4y[v4i];
            float4 vz = p4z[v4i];
            Px[2 * r] = pk2(vx.x, vx.y); Px[2 * r + 1] = pk2(vx.z, vx.w);
            Py[2 * r] = pk2(vy.x, vy.y); Py[2 * r + 1] = pk2(vy.z, vy.w);
            Pz[2 * r] = pk2(vz.x, vz.y); Pz[2 * r + 1] = pk2(vz.z, vz.w);
        }
        float dist[PPT];
#pragma unroll
        for (int k = 0; k < PPT; k++) dist[k] = 1e10f;

        // per-lane remote addrs: lane r (r<8) targets CTA r's
        // slot (rank*4 + w) and mbarrier
        unsigned mbar_l[2], slot_r[2], mbar_r[2];
        int tgt = lane & (FPS_CLU - 1);
#pragma unroll
        for (int pbuf = 0; pbuf < 2; pbuf++) {
            mbar_l[pbuf] = smem_u32(&s_mbar[pbuf]);
            unsigned myslot = smem_u32(&s_mbox[pbuf][rank * (FPS_ACT / 32) + w]);
            slot_r[pbuf] = mapa_rank(myslot, tgt);
            mbar_r[pbuf] = mapa_rank(mbar_l[pbuf], tgt);
        }

        int far = 0;
        for (int it = 0; it < NS; it++) {
            int buf = it & 1;
            unsigned parity = (it >> 1) & 1;
            if (rank == 0 && tid == 0)
                *(volatile int*)&g_fps[b * NS + it] = far + 1;  // payload==flag
            if (tid == 0) mbar_expect_tx(mbar_l[buf], 8 * NSLOT);

            float cx = sx[far], cy = sy[far], cz = sz[far];
            unsigned long long nx = pk2(-cx, -cx);
            unsigned long long ny = pk2(-cy, -cy);
            unsigned long long nz = pk2(-cz, -cz);

            float bv = -1.0f;
            int bi = 0;
#pragma unroll
            for (int q = 0; q < NPAIR; q++) {
                unsigned long long dx = addx2(Px[q], nx);   // x - cx (exact)
                unsigned long long dy = addx2(Py[q], ny);
                unsigned long long dz = addx2(Pz[q], nz);
                unsigned long long s1 = addx2(mulx2(dx, dx), mulx2(dy, dy));
                unsigned long long d2 = addx2(s1, mulx2(dz, dz));
                float d0, d1;
                upk2(d0, d1, d2);
                float n0 = fminf(dist[2 * q], d0);     dist[2 * q] = n0;
                float n1 = fminf(dist[2 * q + 1], d1); dist[2 * q + 1] = n1;
                float pm = fmaxf(n0, n1);
                int   pj = (n0 >= n1) ? (base + 2 * q) : (base + 2 * q + 1);
                if (pm > bv) { bv = pm; bi = pj; }     // strict >: earlier pair wins ties
            }
            // warp argmax via REDUX (dist >= 0: float-bit order == u32 order);
            // lowest winning lane == lowest index
            unsigned dbits = __float_as_uint(bv);
            unsigned mx = __reduce_max_sync(0xffffffffu, dbits);
            unsigned msk = __ballot_sync(0xffffffffu, dbits == mx);
            int src = __ffs(msk) - 1;
            int bi_w = __shfl_sync(0xffffffffu, bi, src);
            unsigned long long key = ((unsigned long long)mx << 32) | (unsigned)bi_w;
            if (lane < FPS_CLU)
                st_async_u64(slot_r[buf], key, mbar_r[buf]);
            mbar_wait(mbar_l[buf], parity);
            // receive: lane i reads slot i; slots index-range-ordered ->
            // lowest winning slot == lowest index
            unsigned long long kk = s_mbox[buf][lane];
            unsigned hd = (unsigned)(kk >> 32);
            unsigned mx2 = __reduce_max_sync(0xffffffffu, hd);
            unsigned msk2 = __ballot_sync(0xffffffffu, hd == mx2);
            int s2 = __ffs(msk2) - 1;
            far = (int)__shfl_sync(0xffffffffu, (unsigned)kk, s2);
        }
    }
    asm volatile("barrier.cluster.arrive.aligned;" ::: "memory");
    asm volatile("barrier.cluster.wait.aligned;" ::: "memory");
}

// ============================================================
// SA role: 64 CTAs, each warp processes 8 centroids in publish
// order (G = said*8 + w + k*512). In-CTA BN fold once; spin on
// g_fps flag per centroid; ball query / MLP / maxpool identical.
// ============================================================
__device__ __noinline__ void sa_role(
    const float* __restrict__ xyz, const float* __restrict__ pts,
    const float* __restrict__ w1, const float* __restrict__ b1,
    const float* __restrict__ g1, const float* __restrict__ t1,
    const float* __restrict__ m1, const float* __restrict__ v1,
    const float* __restrict__ w2, const float* __restrict__ b2,
    const float* __restrict__ g2, const float* __restrict__ t2,
    const float* __restrict__ m2, const float* __restrict__ v2,
    const float* __restrict__ w3, const float* __restrict__ b3,
    const float* __restrict__ g3, const float* __restrict__ t3,
    const float* __restrict__ m3, const float* __restrict__ v3,
    float* __restrict__ out, float* smf)
{
    float* sW1 = smf;                // 384
    float* sB1 = sW1 + 384;          // 64
    float* sW2 = sB1 + 64;           // 4096
    float* sB2 = sW2 + 4096;         // 64
    float* sW3 = sB2 + 64;           // 8192
    float* sB3 = sW3 + 8192;         // 128
    float* sc1 = sB3 + 128;          // 64
    float* sc2 = sc1 + 64;           // 64
    float* sc3 = sc2 + 64;           // 128
    int*   sNbr = (int*)(sc3 + 128); // 8 warps * 32

    int tid = threadIdx.x;

    // ---- per-channel scales + folded biases ----
    if (tid < 64) {
        float s1 = g1[tid] / sqrtf(v1[tid] + 1e-5f);
        sc1[tid] = s1;
        sB1[tid] = (b1[tid] - m1[tid]) * s1 + t1[tid];
        float s2 = g2[tid] / sqrtf(v2[tid] + 1e-5f);
        sc2[tid] = s2;
        sB2[tid] = (b2[tid] - m2[tid]) * s2 + t2[tid];
    } else if (tid < 192) {
        int o = tid - 64;
        float s3 = g3[o] / sqrtf(v3[o] + 1e-5f);
        sc3[o] = s3;
        sB3[o] = (b3[o] - m3[o]) * s3 + t3[o];
    }
    __syncthreads();

    // ---- fold weights while staging ----
    for (int i = tid; i < 384; i += THR) sW1[i] = w1[i] * sc1[i / 6];
    for (int i = tid; i < 4096; i += THR) sW2[i] = w2[i] * sc2[i >> 6];
    for (int i = tid; i < 8192; i += THR) sW3[i] = w3[i] * sc3[i >> 6];
    __syncthreads();

    int w = tid >> 5, lane = tid & 31;
    int said = blockIdx.x - NFPS_CTA;  // 0..63
    int g = said * 8 + w;              // 0..511
    int* nbr = sNbr + w * 32;

    for (int k = 0; k < 8; k++) {
        int G = g + k * 512;           // 0..4095, ascending publish order
        int b = G >> 10;
        int s = G & (NS - 1);

        const float* px = xyz + (size_t)b * 3 * NPTS;
        const float* py = px + NPTS;
        const float* pz = px + 2 * NPTS;
        const float* qx = pts + (size_t)b * 3 * NPTS;
        const float* qy = qx + NPTS;
        const float* qz = qx + 2 * NPTS;

        // ---- spin until FPS publishes this centroid (value = idx+1) ----
        int ci;
        {
            volatile int* flag = &g_fps[b * NS + s];
            int v = *flag;
            while (v == 0) { __nanosleep(200); v = *flag; }
            ci = v - 1;
        }

        float cx = px[ci], cy = py[ci], cz = pz[ci];
        float asq = __fadd_rn(__fadd_rn(__fmul_rn(cx, cx), __fmul_rn(cy, cy)),
                              __fmul_rn(cz, cz));

        // ---- ball query: first NK indices (ascending) with sq <= r^2 ----
        int cnt = 0;
        for (int c0 = 0; c0 < NPTS; c0 += 32) {
            int j = c0 + lane;
            float x = px[j], y = py[j], z = pz[j];
            float bsqj = __fadd_rn(__fadd_rn(__fmul_rn(x, x), __fmul_rn(y, y)),
                                   __fmul_rn(z, z));
            float dot = __fadd_rn(__fadd_rn(__fmul_rn(cx, x), __fmul_rn(cy, y)),
                                  __fmul_rn(cz, z));
            float sq = __fsub_rn(__fadd_rn(asq, bsqj), __fmul_rn(2.0f, dot));
            bool inb = !(sq > R2C);
            unsigned mask = __ballot_sync(0xffffffffu, inb);
            if (mask) {
                int slot = cnt + __popc(mask & ((1u << lane) - 1u));
                if (inb && slot < NK) nbr[slot] = j;
                cnt += __popc(mask);
                if (cnt >= NK) break;
            }
        }
        __syncwarp();
        int myj = nbr[lane < cnt ? lane : 0];

        // ---- gather: 6 input features for this lane's neighbor ----
        float in0 = px[myj] - cx;
        float in1 = py[myj] - cy;
        float in2 = pz[myj] - cz;
        float in3 = qx[myj];
        float in4 = qy[myj];
        float in5 = qz[myj];

        // ---- layer 1: 6 -> 64 ----
        float h1[64];
#pragma unroll
        for (int o = 0; o < 64; o++) {
            const float* wr = sW1 + o * 6;
            float a = sB1[o];
            a = fmaf(wr[0], in0, a);
            a = fmaf(wr[1], in1, a);
            a = fmaf(wr[2], in2, a);
            a = fmaf(wr[3], in3, a);
            a = fmaf(wr[4], in4, a);
            a = fmaf(wr[5], in5, a);
            h1[o] = fmaxf(a, 0.0f);
        }

        // ---- layer 2: 64 -> 64 ----
        float h2[64];
#pragma unroll
        for (int o = 0; o < 64; o++) {
            const float4* wr = (const float4*)(sW2 + (o << 6));
            float a = sB2[o];
#pragma unroll
            for (int c = 0; c < 16; c++) {
                float4 wv = wr[c];
                a = fmaf(wv.x, h1[4 * c + 0], a);
                a = fmaf(wv.y, h1[4 * c + 1], a);
                a = fmaf(wv.z, h1[4 * c + 2], a);
                a = fmaf(wv.w, h1[4 * c + 3], a);
            }
            h2[o] = fmaxf(a, 0.0f);
        }

        // ---- layer 3: 64 -> 128, fused warp-max over the 32 neighbors ----
        float* ob = out + ((size_t)b * 128) * NS + s;
#pragma unroll 1
        for (int o = 0; o < 128; o++) {
            const float4* wr = (const float4*)(sW3 + (o << 6));
            float a = sB3[o];
#pragma unroll
            for (int c = 0; c < 16; c++) {
                float4 wv = wr[c];
                a = fmaf(wv.x, h2[4 * c + 0], a);
                a = fmaf(wv.y, h2[4 * c + 1], a);
                a = fmaf(wv.z, h2[4 * c + 2], a);
                a = fmaf(wv.w, h2[4 * c + 3], a);
            }
            a = fmaxf(a, 0.0f);
#pragma unroll
            for (int off = 16; off; off >>= 1)
                a = fmaxf(a, __shfl_xor_sync(0xffffffffu, a, off));
            if (lane == (o & 31)) ob[(size_t)o * NS] = a;
        }
    }
}

// ============================================================
// fused kernel: CTAs 0..31 = FPS (4 clusters of 8),
// CTAs 32..95 = SA (1 CTA/SM everywhere: grid 96 < 148 SMs)
// ============================================================
__global__ void __cluster_dims__(FPS_CLU, 1, 1) __launch_bounds__(THR, 1)
fused_kernel(
    const float* __restrict__ xyz, const float* __restrict__ pts,
    const float* __restrict__ w1, const float* __restrict__ b1,
    const float* __restrict__ g1, const float* __restrict__ t1,
    const float* __restrict__ m1, const float* __restrict__ v1,
    const float* __restrict__ w2, const float* __restrict__ b2,
    const float* __restrict__ g2, const float* __restrict__ t2,
    const float* __restrict__ m2, const float* __restrict__ v2,
    const float* __restrict__ w3, const float* __restrict__ b3,
    const float* __restrict__ g3, const float* __restrict__ t3,
    const float* __restrict__ m3, const float* __restrict__ v3,
    float* __restrict__ out)
{
    extern __shared__ float smf[];
    if (blockIdx.x < NFPS_CTA) {
        fps_role(xyz, smf);
    } else {
        sa_role(xyz, pts, w1, b1, g1, t1, m1, v1,
                w2, b2, g2, t2, m2, v2,
                w3, b3, g3, t3, m3, v3, out, smf);
    }
}

// ============================================================
extern "C" void kernel_launch(void* const* d_in, const int* in_sizes, int n_in,
                              void* d_out, int out_size)
{
    const float* xyz = (const float*)d_in[0];
    const float* pts = (const float*)d_in[1];
    const float* w1 = (const float*)d_in[2];
    const float* b1 = (const float*)d_in[3];
    const float* g1 = (const float*)d_in[4];
    const float* t1 = (const float*)d_in[5];
    const float* m1 = (const float*)d_in[6];
    const float* v1 = (const float*)d_in[7];
    const float* w2 = (const float*)d_in[8];
    const float* b2 = (const float*)d_in[9];
    const float* g2 = (const float*)d_in[10];
    const float* t2 = (const float*)d_in[11];
    const float* m2 = (const float*)d_in[12];
    const float* v2 = (const float*)d_in[13];
    const float* w3 = (const float*)d_in[14];
    const float* b3 = (const float*)d_in[15];
    const float* g3 = (const float*)d_in[16];
    const float* t3 = (const float*)d_in[17];
    const float* m3 = (const float*)d_in[18];
    const float* v3 = (const float*)d_in[19];

    cudaFuncSetAttribute(fused_kernel, cudaFuncAttributeMaxDynamicSharedMemorySize,
                         SMEM_BYTES);

    fused_kernel<<<NFPS_CTA + NSA_CTA, THR, SMEM_BYTES>>>(
        xyz, pts, w1, b1, g1, t1, m1, v1,
        w2, b2, g2, t2, m2, v2,
        w3, b3, g3, t3, m3, v3, (float*)d_out);
}

// round 14
// speedup vs baseline: 1.1219x; 1.1219x over previous
#include <cuda_runtime.h>
#include <math.h>

#define NB 4
#define NPTS 8192
#define NS 1024
#define NK 32
#define R2C 0.01f
#define FPS_CLU 8
#define THR 256
#define FPS_ACT 128                       // active FPS threads per CTA
#define PPT (NPTS / FPS_CLU / FPS_ACT)    // 8 points per thread
#define NPAIR (PPT / 2)                   // 4 pairs
#define NSLOT (FPS_CLU * (FPS_ACT / 32))  // 32 mailbox slots = 32 lanes
#define NFPS_CTA (NB * FPS_CLU)           // 32 FPS CTAs
#define SMEM_BYTES (3 * NPTS * 4)         // 96 KB

// ---- device scratch (no allocations allowed) ----
__device__ int g_fps[NB * NS];            // stores far+1 (0 = not ready)

// ---- packed f32x2 helpers (per-half IEEE rn => bitwise == scalar) ----
__device__ __forceinline__ unsigned long long pk2(float lo, float hi) {
    unsigned long long r;
    asm("mov.b64 %0, {%1, %2};" : "=l"(r) : "f"(lo), "f"(hi));
    return r;
}
__device__ __forceinline__ void upk2(float& lo, float& hi, unsigned long long v) {
    asm("mov.b64 {%0, %1}, %2;" : "=f"(lo), "=f"(hi) : "l"(v));
}
__device__ __forceinline__ unsigned long long addx2(unsigned long long a, unsigned long long b) {
    unsigned long long r;
    asm("add.rn.f32x2 %0, %1, %2;" : "=l"(r) : "l"(a), "l"(b));
    return r;
}
__device__ __forceinline__ unsigned long long mulx2(unsigned long long a, unsigned long long b) {
    unsigned long long r;
    asm("mul.rn.f32x2 %0, %1, %2;" : "=l"(r) : "l"(a), "l"(b));
    return r;
}

// ---- cluster helpers ----
__device__ __forceinline__ unsigned smem_u32(const void* p) {
    return (unsigned)__cvta_generic_to_shared(p);
}
__device__ __forceinline__ unsigned mapa_rank(unsigned addr, unsigned rank) {
    unsigned r;
    asm("mapa.shared::cluster.u32 %0, %1, %2;" : "=r"(r) : "r"(addr), "r"(rank));
    return r;
}
__device__ __forceinline__ void st_async_u64(unsigned raddr, unsigned long long v, unsigned rmbar) {
    asm volatile("st.async.shared::cluster.mbarrier::complete_tx::bytes.b64 [%0], %1, [%2];"
                 :: "r"(raddr), "l"(v), "r"(rmbar) : "memory");
}
__device__ __forceinline__ void mbar_init(unsigned mbar, unsigned cnt) {
    asm volatile("mbarrier.init.shared.b64 [%0], %1;" :: "r"(mbar), "r"(cnt) : "memory");
}
__device__ __forceinline__ void mbar_expect_tx(unsigned mbar, unsigned bytes) {
    asm volatile("mbarrier.arrive.expect_tx.shared.b64 _, [%0], %1;" :: "r"(mbar), "r"(bytes) : "memory");
}
__device__ __forceinline__ void mbar_wait(unsigned mbar, unsigned parity) {
    asm volatile(
        "{\n\t.reg .pred P;\n"
        "LW%=:\n\t"
        "mbarrier.try_wait.parity.acquire.cluster.shared::cta.b64 P, [%0], %1;\n\t"
        "@P bra LD%=;\n\t"
        "bra LW%=;\n"
        "LD%=:\n\t}"
        :: "r"(mbar), "r"(parity) : "memory");
}

// ============================================================
// FPS role: clusters 0..NB-1 (CTAs 0..31). Warps 0-3 active.
// st.async + mbarrier exchange (R7/R11-proven optimum).
// Exact fp32 op order of the reference throughout.
// ============================================================
__device__ __noinline__ void fps_role(const float* __restrict__ xyz, float* smf)
{
    float* sx = smf;
    float* sy = smf + NPTS;
    float* sz = smf + 2 * NPTS;
    __shared__ unsigned long long s_mbox[2][NSLOT];
    __shared__ unsigned long long s_mbar[2];

    int tid = threadIdx.x;
    int lane = tid & 31, w = tid >> 5;
    int rank = blockIdx.x & (FPS_CLU - 1);
    int b = blockIdx.x / FPS_CLU;
    const float* p = xyz + (size_t)b * 3 * NPTS;

    // full coordinate copy into smem (centroid lookup) — all 256 threads
    const float4* p4x = (const float4*)p;
    const float4* p4y = (const float4*)(p + NPTS);
    const float4* p4z = (const float4*)(p + 2 * NPTS);
    for (int i = tid; i < NPTS / 4; i += THR) {
        ((float4*)sx)[i] = p4x[i];
        ((float4*)sy)[i] = p4y[i];
        ((float4*)sz)[i] = p4z[i];
    }

    if (tid == 0) {
        mbar_init(smem_u32(&s_mbar[0]), 1);
        mbar_init(smem_u32(&s_mbar[1]), 1);
    }
    __syncthreads();
    asm volatile("barrier.cluster.arrive.aligned;" ::: "memory");
    asm volatile("barrier.cluster.wait.aligned;" ::: "memory");

    if (tid < FPS_ACT) {
        // this thread's 8 points (register-resident, packed)
        int base = rank * (NPTS / FPS_CLU) + tid * PPT;
        unsigned long long Px[NPAIR], Py[NPAIR], Pz[NPAIR];
#pragma unroll
        for (int r = 0; r < PPT / 4; r++) {
            int v4i = base / 4 + r;
            float4 vx = p4x[v4i];
            float4 vy = p4y[v4i];
            float4 vz = p4z[v4i];
            Px[2 * r] = pk2(vx.x, vx.y); Px[2 * r + 1] = pk2(vx.z, vx.w);
            Py[2 * r] = pk2(vy.x, vy.y); Py[2 * r + 1] = pk2(vy.z, vy.w);
            Pz[2 * r] = pk2(vz.x, vz.y); Pz[2 * r + 1] = pk2(vz.z, vz.w);
        }
        float dist[PPT];
#pragma unroll
        for (int k = 0; k < PPT; k++) dist[k] = 1e10f;

        // per-lane remote addrs: lane r (r<8) targets CTA r's
        // slot (rank*4 + w) and mbarrier
        unsigned mbar_l[2], slot_r[2], mbar_r[2];
        int tgt = lane & (FPS_CLU - 1);
#pragma unroll
        for (int pbuf = 0; pbuf < 2; pbuf++) {
            mbar_l[pbuf] = smem_u32(&s_mbar[pbuf]);
            unsigned myslot = smem_u32(&s_mbox[pbuf][rank * (FPS_ACT / 32) + w]);
            slot_r[pbuf] = mapa_rank(myslot, tgt);
            mbar_r[pbuf] = mapa_rank(mbar_l[pbuf], tgt);
        }

        int far = 0;
        for (int it = 0; it < NS; it++) {
            int buf = it & 1;
            unsigned parity = (it >> 1) & 1;
            if (rank == 0 && tid == 0)
                *(volatile int*)&g_fps[b * NS + it] = far + 1;  // payload==flag
            if (tid == 0) mbar_expect_tx(mbar_l[buf], 8 * NSLOT);

            float cx = sx[far], cy = sy[far], cz = sz[far];
            unsigned long long nx = pk2(-cx, -cx);
            unsigned long long ny = pk2(-cy, -cy);
            unsigned long long nz = pk2(-cz, -cz);

            float bv = -1.0f;
            int bi = 0;
#pragma unroll
            for (int q = 0; q < NPAIR; q++) {
                unsigned long long dx = addx2(Px[q], nx);   // x - cx (exact)
                unsigned long long dy = addx2(Py[q], ny);
                unsigned long long dz = addx2(Pz[q], nz);
                unsigned long long s1 = addx2(mulx2(dx, dx), mulx2(dy, dy));
                unsigned long long d2 = addx2(s1, mulx2(dz, dz));
                float d0, d1;
                upk2(d0, d1, d2);
                float n0 = fminf(dist[2 * q], d0);     dist[2 * q] = n0;
                float n1 = fminf(dist[2 * q + 1], d1); dist[2 * q + 1] = n1;
                float pm = fmaxf(n0, n1);
                int   pj = (n0 >= n1) ? (base + 2 * q) : (base + 2 * q + 1);
                if (pm > bv) { bv = pm; bi = pj; }     // strict >: earlier pair wins ties
            }
            // warp argmax via REDUX (dist >= 0: float-bit order == u32 order);
            // lowest winning lane == lowest index
            unsigned dbits = __float_as_uint(bv);
            unsigned mx = __reduce_max_sync(0xffffffffu, dbits);
            unsigned msk = __ballot_sync(0xffffffffu, dbits == mx);
            int src = __ffs(msk) - 1;
            int bi_w = __shfl_sync(0xffffffffu, bi, src);
            unsigned long long key = ((unsigned long long)mx << 32) | (unsigned)bi_w;
            if (lane < FPS_CLU)
                st_async_u64(slot_r[buf], key, mbar_r[buf]);
            mbar_wait(mbar_l[buf], parity);
            // receive: lane i reads slot i; slots index-range-ordered ->
            // lowest winning slot == lowest index
            unsigned long long kk = s_mbox[buf][lane];
            unsigned hd = (unsigned)(kk >> 32);
            unsigned mx2 = __reduce_max_sync(0xffffffffu, hd);
            unsigned msk2 = __ballot_sync(0xffffffffu, hd == mx2);
            int s2 = __ffs(msk2) - 1;
            far = (int)__shfl_sync(0xffffffffu, (unsigned)kk, s2);
        }
    }
    asm volatile("barrier.cluster.arrive.aligned;" ::: "memory");
    asm volatile("barrier.cluster.wait.aligned;" ::: "memory");
}

// ============================================================
// SA role: in-CTA BN fold, spin on g_fps flag, ball query
// (bsq inline, exact order), MLP, maxpool. One warp/centroid.
// ============================================================
__device__ __noinline__ void sa_role(
    const float* __restrict__ xyz, const float* __restrict__ pts,
    const float* __restrict__ w1, const float* __restrict__ b1,
    const float* __restrict__ g1, const float* __restrict__ t1,
    const float* __restrict__ m1, const float* __restrict__ v1,
    const float* __restrict__ w2, const float* __restrict__ b2,
    const float* __restrict__ g2, const float* __restrict__ t2,
    const float* __restrict__ m2, const float* __restrict__ v2,
    const float* __restrict__ w3, const float* __restrict__ b3,
    const float* __restrict__ g3, const float* __restrict__ t3,
    const float* __restrict__ m3, const float* __restrict__ v3,
    float* __restrict__ out, float* smf)
{
    float* sW1 = smf;                // 384
    float* sB1 = sW1 + 384;          // 64
    float* sW2 = sB1 + 64;           // 4096
    float* sB2 = sW2 + 4096;         // 64
    float* sW3 = sB2 + 64;           // 8192
    float* sB3 = sW3 + 8192;         // 128
    float* sc1 = sB3 + 128;          // 64
    float* sc2 = sc1 + 64;           // 64
    float* sc3 = sc2 + 64;           // 128
    int*   sNbr = (int*)(sc3 + 128); // 8 warps * 32

    int tid = threadIdx.x;

    // ---- per-channel scales + folded biases ----
    if (tid < 64) {
        float s1 = g1[tid] / sqrtf(v1[tid] + 1e-5f);
        sc1[tid] = s1;
        sB1[tid] = (b1[tid] - m1[tid]) * s1 + t1[tid];
        float s2 = g2[tid] / sqrtf(v2[tid] + 1e-5f);
        sc2[tid] = s2;
        sB2[tid] = (b2[tid] - m2[tid]) * s2 + t2[tid];
    } else if (tid < 192) {
        int o = tid - 64;
        float s3 = g3[o] / sqrtf(v3[o] + 1e-5f);
        sc3[o] = s3;
        sB3[o] = (b3[o] - m3[o]) * s3 + t3[o];
    }
    __syncthreads();

    // ---- fold weights while staging ----
    for (int i = tid; i < 384; i += THR) sW1[i] = w1[i] * sc1[i / 6];
    for (int i = tid; i < 4096; i += THR) sW2[i] = w2[i] * sc2[i >> 6];
    for (int i = tid; i < 8192; i += THR) sW3[i] = w3[i] * sc3[i >> 6];
    __syncthreads();

    int w = tid >> 5, lane = tid & 31;
    int said = blockIdx.x - NFPS_CTA;  // 0..511
    int b = said >> 7;
    int s = ((said & 127) << 3) + w;

    const float* px = xyz + (size_t)b * 3 * NPTS;
    const float* py = px + NPTS;
    const float* pz = px + 2 * NPTS;
    const float* qx = pts + (size_t)b * 3 * NPTS;
    const float* qy = qx + NPTS;
    const float* qz = qx + 2 * NPTS;

    // ---- spin until FPS publishes this centroid (value = idx+1) ----
    int ci;
    {
        volatile int* flag = &g_fps[b * NS + s];
        int v = *flag;
        while (v == 0) { __nanosleep(200); v = *flag; }
        ci = v - 1;
    }

    float cx = px[ci], cy = py[ci], cz = pz[ci];
    float asq = __fadd_rn(__fadd_rn(__fmul_rn(cx, cx), __fmul_rn(cy, cy)),
                          __fmul_rn(cz, cz));

    // ---- ball query: first NK indices (ascending) with sq <= r^2 ----
    int* nbr = sNbr + w * 32;
    int cnt = 0;
    for (int c0 = 0; c0 < NPTS; c0 += 32) {
        int j = c0 + lane;
        float x = px[j], y = py[j], z = pz[j];
        float bsqj = __fadd_rn(__fadd_rn(__fmul_rn(x, x), __fmul_rn(y, y)),
                               __fmul_rn(z, z));
        float dot = __fadd_rn(__fadd_rn(__fmul_rn(cx, x), __fmul_rn(cy, y)),
                              __fmul_rn(cz, z));
        float sq = __fsub_rn(__fadd_rn(asq, bsqj), __fmul_rn(2.0f, dot));
        bool inb = !(sq > R2C);
        unsigned mask = __ballot_sync(0xffffffffu, inb);
        if (mask) {
            int slot = cnt + __popc(mask & ((1u << lane) - 1u));
            if (inb && slot < NK) nbr[slot] = j;
            cnt += __popc(mask);
            if (cnt >= NK) break;
        }
    }
    __syncwarp();
    int myj = nbr[lane < cnt ? lane : 0];

    // ---- gather: 6 input features for this lane's neighbor ----
    float in0 = px[myj] - cx;
    float in1 = py[myj] - cy;
    float in2 = pz[myj] - cz;
    float in3 = qx[myj];
    float in4 = qy[myj];
    float in5 = qz[myj];

    // ---- layer 1: 6 -> 64 ----
    float h1[64];
#pragma unroll
    for (int o = 0; o < 64; o++) {
        const float* wr = sW1 + o * 6;
        float a = sB1[o];
        a = fmaf(wr[0], in0, a);
        a = fmaf(wr[1], in1, a);
        a = fmaf(wr[2], in2, a);
        a = fmaf(wr[3], in3, a);
        a = fmaf(wr[4], in4, a);
        a = fmaf(wr[5], in5, a);
        h1[o] = fmaxf(a, 0.0f);
    }

    // ---- layer 2: 64 -> 64 ----
    float h2[64];
#pragma unroll
    for (int o = 0; o < 64; o++) {
        const float4* wr = (const float4*)(sW2 + (o << 6));
        float a = sB2[o];
#pragma unroll
        for (int c = 0; c < 16; c++) {
            float4 wv = wr[c];
            a = fmaf(wv.x, h1[4 * c + 0], a);
            a = fmaf(wv.y, h1[4 * c + 1], a);
            a = fmaf(wv.z, h1[4 * c + 2], a);
            a = fmaf(wv.w, h1[4 * c + 3], a);
        }
        h2[o] = fmaxf(a, 0.0f);
    }

    // ---- layer 3: 64 -> 128, fused warp-max over the 32 neighbors ----
    float* ob = out + ((size_t)b * 128) * NS + s;
#pragma unroll 1
    for (int o = 0; o < 128; o++) {
        const float4* wr = (const float4*)(sW3 + (o << 6));
        float a = sB3[o];
#pragma unroll
        for (int c = 0; c < 16; c++) {
            float4 wv = wr[c];
            a = fmaf(wv.x, h2[4 * c + 0], a);
            a = fmaf(wv.y, h2[4 * c + 1], a);
            a = fmaf(wv.z, h2[4 * c + 2], a);
            a = fmaf(wv.w, h2[4 * c + 3], a);
        }
        a = fmaxf(a, 0.0f);
#pragma unroll
        for (int off = 16; off; off >>= 1)
            a = fmaxf(a, __shfl_xor_sync(0xffffffffu, a, off));
        if (lane == (o & 31)) ob[(size_t)o * NS] = a;
    }
}

// ============================================================
// fused kernel: clusters 0..3 = FPS, clusters 4..67 = SA
// ============================================================
__global__ void __cluster_dims__(FPS_CLU, 1, 1) __launch_bounds__(THR, 1)
fused_kernel(
    const float* __restrict__ xyz, const float* __restrict__ pts,
    const float* __restrict__ w1, const float* __restrict__ b1,
    const float* __restrict__ g1, const float* __restrict__ t1,
    const float* __restrict__ m1, const float* __restrict__ v1,
    const float* __restrict__ w2, const float* __restrict__ b2,
    const float* __restrict__ g2, const float* __restrict__ t2,
    const float* __restrict__ m2, const float* __restrict__ v2,
    const float* __restrict__ w3, const float* __restrict__ b3,
    const float* __restrict__ g3, const float* __restrict__ t3,
    const float* __restrict__ m3, const float* __restrict__ v3,
    float* __restrict__ out)
{
    extern __shared__ float smf[];
    if (blockIdx.x < NFPS_CTA) {
        fps_role(xyz, smf);
    } else {
        sa_role(xyz, pts, w1, b1, g1, t1, m1, v1,
                w2, b2, g2, t2, m2, v2,
                w3, b3, g3, t3, m3, v3, out, smf);
    }
}

// ============================================================
extern "C" void kernel_launch(void* const* d_in, const int* in_sizes, int n_in,
                              void* d_out, int out_size)
{
    const float* xyz = (const float*)d_in[0];
    const float* pts = (const float*)d_in[1];
    const float* w1 = (const float*)d_in[2];
    const float* b1 = (const float*)d_in[3];
    const float* g1 = (const float*)d_in[4];
    const float* t1 = (const float*)d_in[5];
    const float* m1 = (const float*)d_in[6];
    const float* v1 = (const float*)d_in[7];
    const float* w2 = (const float*)d_in[8];
    const float* b2 = (const float*)d_in[9];
    const float* g2 = (const float*)d_in[10];
    const float* t2 = (const float*)d_in[11];
    const float* m2 = (const float*)d_in[12];
    const float* v2 = (const float*)d_in[13];
    const float* w3 = (const float*)d_in[14];
    const float* b3 = (const float*)d_in[15];
    const float* g3 = (const float*)d_in[16];
    const float* t3 = (const float*)d_in[17];
    const float* m3 = (const float*)d_in[18];
    const float* v3 = (const float*)d_in[19];

    cudaFuncSetAttribute(fused_kernel, cudaFuncAttributeMaxDynamicSharedMemorySize,
                         SMEM_BYTES);

    fused_kernel<<<NFPS_CTA + 512, THR, SMEM_BYTES>>>(
        xyz, pts, w1, b1, g1, t1, m1, v1,
        w2, b2, g2, t2, m2, v2,
        w3, b3, g3, t3, m3, v3, (float*)d_out);
}

// round 15
// speedup vs baseline: 1.1258x; 1.0035x over previous
#include <cuda_runtime.h>
#include <math.h>

#define NB 4
#define NPTS 8192
#define NS 1024
#define NK 32
#define R2C 0.01f
#define FPS_CLU 8
#define THR 256
#define FPS_ACT 128                       // active FPS threads per CTA
#define PPT (NPTS / FPS_CLU / FPS_ACT)    // 8 points per thread
#define NPAIR (PPT / 2)                   // 4 pairs
#define NSLOT (FPS_CLU * (FPS_ACT / 32))  // 32 mailbox slots = 32 lanes
#define NFPS_CTA (NB * FPS_CLU)           // 32 FPS CTAs
#define SMEM_BYTES (3 * NPTS * 4)         // 96 KB

// ---- device scratch (no allocations allowed) ----
__device__ int g_fps[NB * NS];            // stores far+1 (0 = not ready)

// ---- packed f32x2 helpers (per-half IEEE rn => bitwise == scalar) ----
__device__ __forceinline__ unsigned long long pk2(float lo, float hi) {
    unsigned long long r;
    asm("mov.b64 %0, {%1, %2};" : "=l"(r) : "f"(lo), "f"(hi));
    return r;
}
__device__ __forceinline__ void upk2(float& lo, float& hi, unsigned long long v) {
    asm("mov.b64 {%0, %1}, %2;" : "=f"(lo), "=f"(hi) : "l"(v));
}
__device__ __forceinline__ unsigned long long addx2(unsigned long long a, unsigned long long b) {
    unsigned long long r;
    asm("add.rn.f32x2 %0, %1, %2;" : "=l"(r) : "l"(a), "l"(b));
    return r;
}
__device__ __forceinline__ unsigned long long mulx2(unsigned long long a, unsigned long long b) {
    unsigned long long r;
    asm("mul.rn.f32x2 %0, %1, %2;" : "=l"(r) : "l"(a), "l"(b));
    return r;
}

// ---- cluster helpers ----
__device__ __forceinline__ unsigned smem_u32(const void* p) {
    return (unsigned)__cvta_generic_to_shared(p);
}
__device__ __forceinline__ unsigned mapa_rank(unsigned addr, unsigned rank) {
    unsigned r;
    asm("mapa.shared::cluster.u32 %0, %1, %2;" : "=r"(r) : "r"(addr), "r"(rank));
    return r;
}
__device__ __forceinline__ void st_async_u64(unsigned raddr, unsigned long long v, unsigned rmbar) {
    asm volatile("st.async.shared::cluster.mbarrier::complete_tx::bytes.b64 [%0], %1, [%2];"
                 :: "r"(raddr), "l"(v), "r"(rmbar) : "memory");
}
__device__ __forceinline__ void mbar_init(unsigned mbar, unsigned cnt) {
    asm volatile("mbarrier.init.shared.b64 [%0], %1;" :: "r"(mbar), "r"(cnt) : "memory");
}
__device__ __forceinline__ void mbar_expect_tx(unsigned mbar, unsigned bytes) {
    asm volatile("mbarrier.arrive.expect_tx.shared.b64 _, [%0], %1;" :: "r"(mbar), "r"(bytes) : "memory");
}
__device__ __forceinline__ void mbar_wait(unsigned mbar, unsigned parity) {
    asm volatile(
        "{\n\t.reg .pred P;\n"
        "LW%=:\n\t"
        "mbarrier.try_wait.parity.acquire.cluster.shared::cta.b64 P, [%0], %1;\n\t"
        "@P bra LD%=;\n\t"
        "bra LW%=;\n"
        "LD%=:\n\t}"
        :: "r"(mbar), "r"(parity) : "memory");
}

// ============================================================
// FPS role: clusters 0..NB-1 (CTAs 0..31). Warps 0-3 active.
// st.async + mbarrier exchange (triply-reproduced optimum).
// Exact fp32 op order of the reference throughout.
// ============================================================
__device__ __noinline__ void fps_role(const float* __restrict__ xyz, float* smf)
{
    float* sx = smf;
    float* sy = smf + NPTS;
    float* sz = smf + 2 * NPTS;
    __shared__ unsigned long long s_mbox[2][NSLOT];
    __shared__ unsigned long long s_mbar[2];

    int tid = threadIdx.x;
    int lane = tid & 31, w = tid >> 5;
    int rank = blockIdx.x & (FPS_CLU - 1);
    int b = blockIdx.x / FPS_CLU;
    const float* p = xyz + (size_t)b * 3 * NPTS;

    // full coordinate copy into smem (centroid lookup) — all 256 threads
    const float4* p4x = (const float4*)p;
    const float4* p4y = (const float4*)(p + NPTS);
    const float4* p4z = (const float4*)(p + 2 * NPTS);
    for (int i = tid; i < NPTS / 4; i += THR) {
        ((float4*)sx)[i] = p4x[i];
        ((float4*)sy)[i] = p4y[i];
        ((float4*)sz)[i] = p4z[i];
    }

    if (tid == 0) {
        mbar_init(smem_u32(&s_mbar[0]), 1);
        mbar_init(smem_u32(&s_mbar[1]), 1);
    }
    __syncthreads();
    asm volatile("barrier.cluster.arrive.aligned;" ::: "memory");
    asm volatile("barrier.cluster.wait.aligned;" ::: "memory");

    if (tid < FPS_ACT) {
        // this thread's 8 points (register-resident, packed)
        int base = rank * (NPTS / FPS_CLU) + tid * PPT;
        unsigned long long Px[NPAIR], Py[NPAIR], Pz[NPAIR];
#pragma unroll
        for (int r = 0; r < PPT / 4; r++) {
            int v4i = base / 4 + r;
            float4 vx = p4x[v4i];
            float4 vy = p4y[v4i];
            float4 vz = p4z[v4i];
            Px[2 * r] = pk2(vx.x, vx.y); Px[2 * r + 1] = pk2(vx.z, vx.w);
            Py[2 * r] = pk2(vy.x, vy.y); Py[2 * r + 1] = pk2(vy.z, vy.w);
            Pz[2 * r] = pk2(vz.x, vz.y); Pz[2 * r + 1] = pk2(vz.z, vz.w);
        }
        float dist[PPT];
#pragma unroll
        for (int k = 0; k < PPT; k++) dist[k] = 1e10f;

        // per-lane remote addrs: lane r (r<8) targets CTA r's
        // slot (rank*4 + w) and mbarrier
        unsigned mbar_l[2], slot_r[2], mbar_r[2];
        int tgt = lane & (FPS_CLU - 1);
#pragma unroll
        for (int pbuf = 0; pbuf < 2; pbuf++) {
            mbar_l[pbuf] = smem_u32(&s_mbar[pbuf]);
            unsigned myslot = smem_u32(&s_mbox[pbuf][rank * (FPS_ACT / 32) + w]);
            slot_r[pbuf] = mapa_rank(myslot, tgt);
            mbar_r[pbuf] = mapa_rank(mbar_l[pbuf], tgt);
        }

        int far = 0;
        for (int it = 0; it < NS; it++) {
            int buf = it & 1;
            unsigned parity = (it >> 1) & 1;
            if (rank == 0 && tid == 0)
                *(volatile int*)&g_fps[b * NS + it] = far + 1;  // payload==flag
            if (tid == 0) mbar_expect_tx(mbar_l[buf], 8 * NSLOT);

            float cx = sx[far], cy = sy[far], cz = sz[far];
            unsigned long long nx = pk2(-cx, -cx);
            unsigned long long ny = pk2(-cy, -cy);
            unsigned long long nz = pk2(-cz, -cz);

            float bv = -1.0f;
            int bi = 0;
#pragma unroll
            for (int q = 0; q < NPAIR; q++) {
                unsigned long long dx = addx2(Px[q], nx);   // x - cx (exact)
                unsigned long long dy = addx2(Py[q], ny);
                unsigned long long dz = addx2(Pz[q], nz);
                unsigned long long s1 = addx2(mulx2(dx, dx), mulx2(dy, dy));
                unsigned long long d2 = addx2(s1, mulx2(dz, dz));
                float d0, d1;
                upk2(d0, d1, d2);
                float n0 = fminf(dist[2 * q], d0);     dist[2 * q] = n0;
                float n1 = fminf(dist[2 * q + 1], d1); dist[2 * q + 1] = n1;
                float pm = fmaxf(n0, n1);
                int   pj = (n0 >= n1) ? (base + 2 * q) : (base + 2 * q + 1);
                if (pm > bv) { bv = pm; bi = pj; }     // strict >: earlier pair wins ties
            }
            // warp argmax via REDUX (dist >= 0: float-bit order == u32 order);
            // lowest winning lane == lowest index
            unsigned dbits = __float_as_uint(bv);
            unsigned mx = __reduce_max_sync(0xffffffffu, dbits);
            unsigned msk = __ballot_sync(0xffffffffu, dbits == mx);
            int src = __ffs(msk) - 1;
            int bi_w = __shfl_sync(0xffffffffu, bi, src);
            unsigned long long key = ((unsigned long long)mx << 32) | (unsigned)bi_w;
            if (lane < FPS_CLU)
                st_async_u64(slot_r[buf], key, mbar_r[buf]);
            mbar_wait(mbar_l[buf], parity);
            // receive: lane i reads slot i; slots index-range-ordered ->
            // lowest winning slot == lowest index
            unsigned long long kk = s_mbox[buf][lane];
            unsigned hd = (unsigned)(kk >> 32);
            unsigned mx2 = __reduce_max_sync(0xffffffffu, hd);
            unsigned msk2 = __ballot_sync(0xffffffffu, hd == mx2);
            int s2 = __ffs(msk2) - 1;
            far = (int)__shfl_sync(0xffffffffu, (unsigned)kk, s2);
        }
    }
    asm volatile("barrier.cluster.arrive.aligned;" ::: "memory");
    asm volatile("barrier.cluster.wait.aligned;" ::: "memory");
}

// ============================================================
// SA role: in-CTA BN fold, spin on g_fps flag, ball query
// (bsq inline, exact order), MLP, maxpool. One warp/centroid.
// ============================================================
__device__ __noinline__ void sa_role(
    const float* __restrict__ xyz, const float* __restrict__ pts,
    const float* __restrict__ w1, const float* __restrict__ b1,
    const float* __restrict__ g1, const float* __restrict__ t1,
    const float* __restrict__ m1, const float* __restrict__ v1,
    const float* __restrict__ w2, const float* __restrict__ b2,
    const float* __restrict__ g2, const float* __restrict__ t2,
    const float* __restrict__ m2, const float* __restrict__ v2,
    const float* __restrict__ w3, const float* __restrict__ b3,
    const float* __restrict__ g3, const float* __restrict__ t3,
    const float* __restrict__ m3, const float* __restrict__ v3,
    float* __restrict__ out, float* smf)
{
    float* sW1 = smf;                // 384
    float* sB1 = sW1 + 384;          // 64
    float* sW2 = sB1 + 64;           // 4096
    float* sB2 = sW2 + 4096;         // 64
    float* sW3 = sB2 + 64;           // 8192
    float* sB3 = sW3 + 8192;         // 128
    float* sc1 = sB3 + 128;          // 64
    float* sc2 = sc1 + 64;           // 64
    float* sc3 = sc2 + 64;           // 128
    int*   sNbr = (int*)(sc3 + 128); // 8 warps * 32

    int tid = threadIdx.x;

    // ---- per-channel scales + folded biases ----
    if (tid < 64) {
        float s1 = g1[tid] / sqrtf(v1[tid] + 1e-5f);
        sc1[tid] = s1;
        sB1[tid] = (b1[tid] - m1[tid]) * s1 + t1[tid];
        float s2 = g2[tid] / sqrtf(v2[tid] + 1e-5f);
        sc2[tid] = s2;
        sB2[tid] = (b2[tid] - m2[tid]) * s2 + t2[tid];
    } else if (tid < 192) {
        int o = tid - 64;
        float s3 = g3[o] / sqrtf(v3[o] + 1e-5f);
        sc3[o] = s3;
        sB3[o] = (b3[o] - m3[o]) * s3 + t3[o];
    }
    __syncthreads();

    // ---- fold weights while staging ----
    for (int i = tid; i < 384; i += THR) sW1[i] = w1[i] * sc1[i / 6];
    for (int i = tid; i < 4096; i += THR) sW2[i] = w2[i] * sc2[i >> 6];
    for (int i = tid; i < 8192; i += THR) sW3[i] = w3[i] * sc3[i >> 6];
    __syncthreads();

    int w = tid >> 5, lane = tid & 31;
    int said = blockIdx.x - NFPS_CTA;  // 0..511
    int b = said >> 7;
    int s = ((said & 127) << 3) + w;

    const float* px = xyz + (size_t)b * 3 * NPTS;
    const float* py = px + NPTS;
    const float* pz = px + 2 * NPTS;
    const float* qx = pts + (size_t)b * 3 * NPTS;
    const float* qy = qx + NPTS;
    const float* qz = qx + 2 * NPTS;

    // ---- spin until FPS publishes this centroid (value = idx+1) ----
    int ci;
    {
        volatile int* flag = &g_fps[b * NS + s];
        int v = *flag;
        while (v == 0) { __nanosleep(200); v = *flag; }
        ci = v - 1;
    }

    float cx = px[ci], cy = py[ci], cz = pz[ci];
    float asq = __fadd_rn(__fadd_rn(__fmul_rn(cx, cx), __fmul_rn(cy, cy)),
                          __fmul_rn(cz, cz));

    // ---- ball query: first NK indices (ascending) with sq <= r^2 ----
    int* nbr = sNbr + w * 32;
    int cnt = 0;
    for (int c0 = 0; c0 < NPTS; c0 += 32) {
        int j = c0 + lane;
        float x = px[j], y = py[j], z = pz[j];
        float bsqj = __fadd_rn(__fadd_rn(__fmul_rn(x, x), __fmul_rn(y, y)),
                               __fmul_rn(z, z));
        float dot = __fadd_rn(__fadd_rn(__fmul_rn(cx, x), __fmul_rn(cy, y)),
                              __fmul_rn(cz, z));
        float sq = __fsub_rn(__fadd_rn(asq, bsqj), __fmul_rn(2.0f, dot));
        bool inb = !(sq > R2C);
        unsigned mask = __ballot_sync(0xffffffffu, inb);
        if (mask) {
            int slot = cnt + __popc(mask & ((1u << lane) - 1u));
            if (inb && slot < NK) nbr[slot] = j;
            cnt += __popc(mask);
            if (cnt >= NK) break;
        }
    }
    __syncwarp();
    int myj = nbr[lane < cnt ? lane : 0];

    // ---- gather: 6 input features for this lane's neighbor ----
    float in0 = px[myj] - cx;
    float in1 = py[myj] - cy;
    float in2 = pz[myj] - cz;
    float in3 = qx[myj];
    float in4 = qy[myj];
    float in5 = qz[myj];

    // ---- layer 1: 6 -> 64 ----
    float h1[64];
#pragma unroll
    for (int o = 0; o < 64; o++) {
        const float* wr = sW1 + o * 6;
        float a = sB1[o];
        a = fmaf(wr[0], in0, a);
        a = fmaf(wr[1], in1, a);
        a = fmaf(wr[2], in2, a);
        a = fmaf(wr[3], in3, a);
        a = fmaf(wr[4], in4, a);
        a = fmaf(wr[5], in5, a);
        h1[o] = fmaxf(a, 0.0f);
    }

    // ---- layer 2: 64 -> 64 ----
    float h2[64];
#pragma unroll
    for (int o = 0; o < 64; o++) {
        const float4* wr = (const float4*)(sW2 + (o << 6));
        float a = sB2[o];
#pragma unroll
        for (int c = 0; c < 16; c++) {
            float4 wv = wr[c];
            a = fmaf(wv.x, h1[4 * c + 0], a);
            a = fmaf(wv.y, h1[4 * c + 1], a);
            a = fmaf(wv.z, h1[4 * c + 2], a);
            a = fmaf(wv.w, h1[4 * c + 3], a);
        }
        h2[o] = fmaxf(a, 0.0f);
    }

    // ---- layer 3: 64 -> 128, fused warp-max over the 32 neighbors ----
    float* ob = out + ((size_t)b * 128) * NS + s;
#pragma unroll 1
    for (int o = 0; o < 128; o++) {
        const float4* wr = (const float4*)(sW3 + (o << 6));
        float a = sB3[o];
#pragma unroll
        for (int c = 0; c < 16; c++) {
            float4 wv = wr[c];
            a = fmaf(wv.x, h2[4 * c + 0], a);
            a = fmaf(wv.y, h2[4 * c + 1], a);
            a = fmaf(wv.z, h2[4 * c + 2], a);
            a = fmaf(wv.w, h2[4 * c + 3], a);
        }
        a = fmaxf(a, 0.0f);
#pragma unroll
        for (int off = 16; off; off >>= 1)
            a = fmaxf(a, __shfl_xor_sync(0xffffffffu, a, off));
        if (lane == (o & 31)) ob[(size_t)o * NS] = a;
    }
}

// ============================================================
// fused kernel: clusters 0..3 = FPS, clusters 4..67 = SA
// ============================================================
__global__ void __cluster_dims__(FPS_CLU, 1, 1) __launch_bounds__(THR, 1)
fused_kernel(
    const float* __restrict__ xyz, const float* __restrict__ pts,
    const float* __restrict__ w1, const float* __restrict__ b1,
    const float* __restrict__ g1, const float* __restrict__ t1,
    const float* __restrict__ m1, const float* __restrict__ v1,
    const float* __restrict__ w2, const float* __restrict__ b2,
    const float* __restrict__ g2, const float* __restrict__ t2,
    const float* __restrict__ m2, const float* __restrict__ v2,
    const float* __restrict__ w3, const float* __restrict__ b3,
    const float* __restrict__ g3, const float* __restrict__ t3,
    const float* __restrict__ m3, const float* __restrict__ v3,
    float* __restrict__ out)
{
    extern __shared__ float smf[];
    if (blockIdx.x < NFPS_CTA) {
        fps_role(xyz, smf);
    } else {
        sa_role(xyz, pts, w1, b1, g1, t1, m1, v1,
                w2, b2, g2, t2, m2, v2,
                w3, b3, g3, t3, m3, v3, out, smf);
    }
}

// ============================================================
extern "C" void kernel_launch(void* const* d_in, const int* in_sizes, int n_in,
                              void* d_out, int out_size)
{
    const float* xyz = (const float*)d_in[0];
    const float* pts = (const float*)d_in[1];
    const float* w1 = (const float*)d_in[2];
    const float* b1 = (const float*)d_in[3];
    const float* g1 = (const float*)d_in[4];
    const float* t1 = (const float*)d_in[5];
    const float* m1 = (const float*)d_in[6];
    const float* v1 = (const float*)d_in[7];
    const float* w2 = (const float*)d_in[8];
    const float* b2 = (const float*)d_in[9];
    const float* g2 = (const float*)d_in[10];
    const float* t2 = (const float*)d_in[11];
    const float* m2 = (const float*)d_in[12];
    const float* v2 = (const float*)d_in[13];
    const float* w3 = (const float*)d_in[14];
    const float* b3 = (const float*)d_in[15];
    const float* g3 = (const float*)d_in[16];
    const float* t3 = (const float*)d_in[17];
    const float* m3 = (const float*)d_in[18];
    const float* v3 = (const float*)d_in[19];

    cudaFuncSetAttribute(fused_kernel, cudaFuncAttributeMaxDynamicSharedMemorySize,
                         SMEM_BYTES);

    fused_kernel<<<NFPS_CTA + 512, THR, SMEM_BYTES>>>(
        xyz, pts, w1, b1, g1, t1, m1, v1,
        w2, b2, g2, t2, m2, v2,
        w3, b3, g3, t3, m3, v3, (float*)d_out);
}